// round 1
// baseline (speedup 1.0000x reference)
#include <cuda_runtime.h>

#define N_NODES 16384
#define N_EDGES 131072
#define F_IN 6
#define S_DIM 4
#define G_NUM 256
#define H_DIM 30
#define C1 32
#define C2 64
#define C3 32
#define EN_EDGES (N_EDGES + N_NODES)

// ---------------- scratch (device globals; no runtime allocation) ------------
__device__ float g_H1[N_EDGES * H_DIM];          // ECC1 edge-MLP hidden out
__device__ float g_H2[N_EDGES * H_DIM];          // ECC2 edge-MLP hidden out
__device__ float g_Y1[N_NODES * H_DIM * C1];     // y1[n, h*32+c1]
__device__ float g_Z1[N_NODES * C1];             // bk1 contribution per node
__device__ float g_AGG1[N_NODES * C1];
__device__ float g_X1[N_NODES * C1];
__device__ float g_Y2[N_NODES * H_DIM * C2];     // y2[n, h*64+c2]
__device__ float g_Z2[N_NODES * C2];
__device__ float g_AGG2[N_NODES * C2];
__device__ float g_X2[N_NODES * C2];
__device__ float g_XW[N_NODES * C3];
__device__ float g_ACC3[N_NODES * C3];

// ---------------- zero scratch + output each call ----------------------------
__global__ void k_zero(float* __restrict__ out, int out_n) {
    int i = blockIdx.x * blockDim.x + threadIdx.x;
    if (i < N_NODES * C1) g_AGG1[i] = 0.f;
    if (i < N_NODES * C2) g_AGG2[i] = 0.f;
    if (i < N_NODES * C3) g_ACC3[i] = 0.f;
    if (i < out_n)        out[i]    = 0.f;
}

// ---------------- edge MLPs for both ECC layers ------------------------------
// h0 = relu(e@w0+b0); h1 = relu(h0@w1+b1)  -> store [E,30] per layer
__global__ void k_edge_mlp(const float* __restrict__ e,
                           const float* __restrict__ w0a, const float* __restrict__ b0a,
                           const float* __restrict__ w1a, const float* __restrict__ b1a,
                           const float* __restrict__ w0b, const float* __restrict__ b0b,
                           const float* __restrict__ w1b, const float* __restrict__ b1b) {
    __shared__ float sw0[2][S_DIM * H_DIM];
    __shared__ float sb0[2][H_DIM];
    __shared__ float sw1[2][H_DIM * H_DIM];
    __shared__ float sb1[2][H_DIM];
    for (int i = threadIdx.x; i < S_DIM * H_DIM; i += blockDim.x) {
        sw0[0][i] = w0a[i]; sw0[1][i] = w0b[i];
    }
    for (int i = threadIdx.x; i < H_DIM; i += blockDim.x) {
        sb0[0][i] = b0a[i]; sb0[1][i] = b0b[i];
        sb1[0][i] = b1a[i]; sb1[1][i] = b1b[i];
    }
    for (int i = threadIdx.x; i < H_DIM * H_DIM; i += blockDim.x) {
        sw1[0][i] = w1a[i]; sw1[1][i] = w1b[i];
    }
    __syncthreads();

    int eid = blockIdx.x * blockDim.x + threadIdx.x;
    if (eid >= N_EDGES) return;
    float4 ev4 = *reinterpret_cast<const float4*>(e + eid * 4);
    float ev[4] = {ev4.x, ev4.y, ev4.z, ev4.w};

    #pragma unroll
    for (int set = 0; set < 2; set++) {
        float h0[H_DIM];
        #pragma unroll
        for (int j = 0; j < H_DIM; j++) {
            float a = sb0[set][j];
            #pragma unroll
            for (int s = 0; s < S_DIM; s++) a += ev[s] * sw0[set][s * H_DIM + j];
            h0[j] = fmaxf(a, 0.f);
        }
        float* dst = (set == 0 ? g_H1 : g_H2) + eid * H_DIM;
        #pragma unroll 5
        for (int j = 0; j < H_DIM; j++) {
            float a = sb1[set][j];
            #pragma unroll
            for (int k = 0; k < H_DIM; k++) a += h0[k] * sw1[set][k * H_DIM + j];
            dst[j] = fmaxf(a, 0.f);
        }
    }
}

// ---------------- ECC1 node precompute: y1[n,h*32+c1] = sum_f x[n,f]*wk1[h,f*32+c1]
// cols 0..959 -> y1 ; cols 960..991 -> z1[n,c1] = sum_f x[n,f]*bk1[f*32+c1]
__global__ void k_y1(const float* __restrict__ x,
                     const float* __restrict__ wk1, const float* __restrict__ bk1) {
    __shared__ float sx[F_IN];
    int n = blockIdx.y;
    if (threadIdx.x < F_IN) sx[threadIdx.x] = x[n * F_IN + threadIdx.x];
    __syncthreads();
    int j = blockIdx.x * blockDim.x + threadIdx.x;
    if (j < H_DIM * C1) {
        int h = j >> 5, c = j & 31;
        float a = 0.f;
        #pragma unroll
        for (int f = 0; f < F_IN; f++)
            a += sx[f] * wk1[h * (F_IN * C1) + f * C1 + c];
        g_Y1[n * (H_DIM * C1) + j] = a;
    } else if (j < H_DIM * C1 + C1) {
        int c = j - H_DIM * C1;
        float a = 0.f;
        #pragma unroll
        for (int f = 0; f < F_IN; f++)
            a += sx[f] * bk1[f * C1 + c];
        g_Z1[n * C1 + c] = a;
    }
}

// ---------------- ECC1 edge: warp per edge, lane = c1 ------------------------
__global__ void k_ecc1_edge(const int* __restrict__ src, const int* __restrict__ tgt) {
    int wid = (blockIdx.x * blockDim.x + threadIdx.x) >> 5;
    int lane = threadIdx.x & 31;
    if (wid >= N_EDGES) return;
    int s = src[wid], t = tgt[wid];
    const float* y  = g_Y1 + (long long)s * (H_DIM * C1);
    const float* hh = g_H1 + wid * H_DIM;
    float acc = g_Z1[s * C1 + lane];
    #pragma unroll
    for (int h = 0; h < H_DIM; h++) acc += hh[h] * y[h * C1 + lane];
    atomicAdd(&g_AGG1[t * C1 + lane], acc);
}

// ---------------- ECC1 node update: x1 = relu(agg1 + x@root1 + bias1) --------
__global__ void k_x1(const float* __restrict__ x,
                     const float* __restrict__ root1, const float* __restrict__ bias1) {
    int idx = blockIdx.x * blockDim.x + threadIdx.x;
    if (idx >= N_NODES * C1) return;
    int n = idx >> 5, c = idx & 31;
    float a = g_AGG1[idx] + bias1[c];
    #pragma unroll
    for (int f = 0; f < F_IN; f++) a += x[n * F_IN + f] * root1[f * C1 + c];
    g_X1[idx] = fmaxf(a, 0.f);
}

// ---------------- ECC2 node precompute: y2[n,h*64+c2] = sum_c1 x1[n,c1]*wk2[h,c1*64+c2]
// cols 0..1919 -> y2 ; cols 1920..1983 -> z2
__global__ void k_y2(const float* __restrict__ wk2, const float* __restrict__ bk2) {
    __shared__ float sx[C1];
    int n = blockIdx.y;
    if (threadIdx.x < C1) sx[threadIdx.x] = g_X1[n * C1 + threadIdx.x];
    __syncthreads();
    int j = blockIdx.x * blockDim.x + threadIdx.x;
    if (j < H_DIM * C2) {
        int h = j >> 6, c = j & 63;
        float a = 0.f;
        const float* w = wk2 + h * (C1 * C2) + c;
        #pragma unroll 8
        for (int c1 = 0; c1 < C1; c1++) a += sx[c1] * w[c1 * C2];
        g_Y2[n * (H_DIM * C2) + j] = a;
    } else if (j < H_DIM * C2 + C2) {
        int c = j - H_DIM * C2;
        float a = 0.f;
        #pragma unroll 8
        for (int c1 = 0; c1 < C1; c1++) a += sx[c1] * bk2[c1 * C2 + c];
        g_Z2[n * C2 + c] = a;
    }
}

// ---------------- ECC2 edge: warp per edge, lane handles c2={lane, lane+32} --
__global__ void k_ecc2_edge(const int* __restrict__ src, const int* __restrict__ tgt) {
    int wid = (blockIdx.x * blockDim.x + threadIdx.x) >> 5;
    int lane = threadIdx.x & 31;
    if (wid >= N_EDGES) return;
    int s = src[wid], t = tgt[wid];
    const float* y  = g_Y2 + (long long)s * (H_DIM * C2);
    const float* hh = g_H2 + wid * H_DIM;
    float a0 = g_Z2[s * C2 + lane];
    float a1 = g_Z2[s * C2 + lane + 32];
    #pragma unroll
    for (int h = 0; h < H_DIM; h++) {
        float hv = hh[h];
        a0 += hv * y[h * C2 + lane];
        a1 += hv * y[h * C2 + lane + 32];
    }
    atomicAdd(&g_AGG2[t * C2 + lane], a0);
    atomicAdd(&g_AGG2[t * C2 + lane + 32], a1);
}

// ---------------- ECC2 node update: x2 = relu(agg2 + x1@root2 + bias2) -------
__global__ void k_x2(const float* __restrict__ root2, const float* __restrict__ bias2) {
    int idx = blockIdx.x * blockDim.x + threadIdx.x;
    if (idx >= N_NODES * C2) return;
    int n = idx >> 6, c = idx & 63;
    float a = g_AGG2[idx] + bias2[c];
    #pragma unroll 8
    for (int c1 = 0; c1 < C1; c1++) a += g_X1[n * C1 + c1] * root2[c1 * C2 + c];
    g_X2[idx] = fmaxf(a, 0.f);
}

// ---------------- GCN: xw = x2 @ gcn_W ---------------------------------------
__global__ void k_xw(const float* __restrict__ gcnW) {
    int idx = blockIdx.x * blockDim.x + threadIdx.x;
    if (idx >= N_NODES * C3) return;
    int n = idx >> 5, c = idx & 31;
    float a = 0.f;
    #pragma unroll 8
    for (int c2 = 0; c2 < C2; c2++) a += g_X2[n * C2 + c2] * gcnW[c2 * C3 + c];
    g_XW[idx] = a;
}

// ---------------- GCN weighted scatter (includes self loops) -----------------
__global__ void k_gcn_edge(const int* __restrict__ gsrc, const int* __restrict__ gtgt,
                           const float* __restrict__ gw) {
    int wid = (blockIdx.x * blockDim.x + threadIdx.x) >> 5;
    int lane = threadIdx.x & 31;
    if (wid >= EN_EDGES) return;
    int s = gsrc[wid], t = gtgt[wid];
    float w = gw[wid];
    atomicAdd(&g_ACC3[t * C3 + lane], w * g_XW[s * C3 + lane]);
}

// ---------------- relu + bias + global sum pool ------------------------------
__global__ void k_pool(const int* __restrict__ seg, const float* __restrict__ gcn_b,
                       float* __restrict__ out) {
    int idx = blockIdx.x * blockDim.x + threadIdx.x;
    if (idx >= N_NODES * C3) return;
    int n = idx >> 5, c = idx & 31;
    float v = fmaxf(g_ACC3[idx] + gcn_b[c], 0.f);
    atomicAdd(&out[seg[n] * C3 + c], v);
}

// =============================================================================
extern "C" void kernel_launch(void* const* d_in, const int* in_sizes, int n_in,
                              void* d_out, int out_size) {
    const float* x       = (const float*)d_in[0];
    const float* e       = (const float*)d_in[1];
    const int*   src     = (const int*)d_in[2];
    const int*   tgt     = (const int*)d_in[3];
    const int*   seg     = (const int*)d_in[4];
    const int*   gsrc    = (const int*)d_in[5];
    const int*   gtgt    = (const int*)d_in[6];
    const float* gw      = (const float*)d_in[7];
    const float* e1_w0   = (const float*)d_in[8];
    const float* e1_b0   = (const float*)d_in[9];
    const float* e1_w1   = (const float*)d_in[10];
    const float* e1_b1   = (const float*)d_in[11];
    const float* e1_wk   = (const float*)d_in[12];
    const float* e1_bk   = (const float*)d_in[13];
    const float* e1_root = (const float*)d_in[14];
    const float* e1_bias = (const float*)d_in[15];
    const float* e2_w0   = (const float*)d_in[16];
    const float* e2_b0   = (const float*)d_in[17];
    const float* e2_w1   = (const float*)d_in[18];
    const float* e2_b1   = (const float*)d_in[19];
    const float* e2_wk   = (const float*)d_in[20];
    const float* e2_bk   = (const float*)d_in[21];
    const float* e2_root = (const float*)d_in[22];
    const float* e2_bias = (const float*)d_in[23];
    const float* gcn_W   = (const float*)d_in[24];
    const float* gcn_b   = (const float*)d_in[25];
    float* out = (float*)d_out;

    // zero accumulators + output (out poisoned each run)
    k_zero<<<(N_NODES * C2 + 255) / 256, 256>>>(out, out_size);

    // edge MLPs for both ECC layers
    k_edge_mlp<<<N_EDGES / 256, 256>>>(e, e1_w0, e1_b0, e1_w1, e1_b1,
                                          e2_w0, e2_b0, e2_w1, e2_b1);

    // ECC1
    k_y1<<<dim3(8, N_NODES), 128>>>(x, e1_wk, e1_bk);
    k_ecc1_edge<<<(N_EDGES * 32) / 256, 256>>>(src, tgt);
    k_x1<<<(N_NODES * C1) / 256, 256>>>(x, e1_root, e1_bias);

    // ECC2
    k_y2<<<dim3(16, N_NODES), 128>>>(e2_wk, e2_bk);
    k_ecc2_edge<<<(N_EDGES * 32) / 256, 256>>>(src, tgt);
    k_x2<<<(N_NODES * C2) / 256, 256>>>(e2_root, e2_bias);

    // GCN + pool
    k_xw<<<(N_NODES * C3) / 256, 256>>>(gcn_W);
    k_gcn_edge<<<(EN_EDGES * 32) / 256, 256>>>(gsrc, gtgt, gw);
    k_pool<<<(N_NODES * C3) / 256, 256>>>(seg, gcn_b, out);
}

// round 3
// speedup vs baseline: 1.4865x; 1.4865x over previous
#include <cuda_runtime.h>

#define N_NODES 16384
#define N_EDGES 131072
#define F_IN 6
#define S_DIM 4
#define G_NUM 256
#define H_DIM 30
#define C1 32
#define C2 64
#define C3 32
#define EN_EDGES (N_EDGES + N_NODES)

// ---------------- scratch (device globals; no runtime allocation) ------------
__device__ float g_H1[N_EDGES * H_DIM];
__device__ float g_H2[N_EDGES * H_DIM];
__device__ float g_Y1[N_NODES * H_DIM * C1];
__device__ float g_Z1[N_NODES * C1];
__device__ float g_AGG1[N_NODES * C1];
__device__ float g_X1[N_NODES * C1];
__device__ float g_Y2[N_NODES * H_DIM * C2];
__device__ float g_Z2[N_NODES * C2];
__device__ float g_AGG2[N_NODES * C2];
__device__ float g_X2[N_NODES * C2];
__device__ float g_XW[N_NODES * C3];
__device__ float g_ACC3[N_NODES * C3];
// CSR by src
__device__ int g_deg[N_NODES];
__device__ int g_rowptr[N_NODES + 1];
__device__ int g_cursor[N_NODES];
__device__ int g_csr[N_EDGES];

// ---------------- packed f32x2 helpers ---------------------------------------
__device__ __forceinline__ unsigned long long pk2(float lo, float hi) {
    unsigned long long r;
    asm("mov.b64 %0, {%1, %2};" : "=l"(r) : "f"(lo), "f"(hi));
    return r;
}
__device__ __forceinline__ void upk2(unsigned long long v, float& lo, float& hi) {
    asm("mov.b64 {%0, %1}, %2;" : "=f"(lo), "=f"(hi) : "l"(v));
}
__device__ __forceinline__ unsigned long long fma2(unsigned long long a,
                                                   unsigned long long b,
                                                   unsigned long long c) {
    unsigned long long d;
    asm("fma.rn.f32x2 %0, %1, %2, %3;" : "=l"(d) : "l"(a), "l"(b), "l"(c));
    return d;
}

// ---------------- zero scratch + output each call ----------------------------
__global__ void k_zero(float* __restrict__ out, int out_n) {
    int i = blockIdx.x * blockDim.x + threadIdx.x;
    if (i < N_NODES * C1) g_AGG1[i] = 0.f;
    if (i < N_NODES * C2) g_AGG2[i] = 0.f;
    if (i < N_NODES * C3) g_ACC3[i] = 0.f;
    if (i < N_NODES)      g_deg[i]  = 0;
    if (i < out_n)        out[i]    = 0.f;
}

// ---------------- CSR build --------------------------------------------------
__global__ void k_hist(const int* __restrict__ src) {
    int e = blockIdx.x * blockDim.x + threadIdx.x;
    if (e < N_EDGES) atomicAdd(&g_deg[src[e]], 1);
}

__global__ void k_scan() {  // 1 block, 1024 threads, 16 elems/thread
    __shared__ int part[1024];
    int tid = threadIdx.x;
    int base = tid * 16;
    int loc[16];
    int s = 0;
    #pragma unroll
    for (int i = 0; i < 16; i++) { loc[i] = s; s += g_deg[base + i]; }
    int val = s;
    part[tid] = s;
    __syncthreads();
    for (int d = 1; d < 1024; d <<= 1) {
        int t = (tid >= d) ? part[tid - d] : 0;
        __syncthreads();
        part[tid] += t;
        __syncthreads();
    }
    int off = part[tid] - val;
    #pragma unroll
    for (int i = 0; i < 16; i++) {
        g_rowptr[base + i] = off + loc[i];
        g_cursor[base + i] = off + loc[i];
    }
    if (tid == 1023) g_rowptr[N_NODES] = off + val;
}

__global__ void k_scatter(const int* __restrict__ src) {
    int e = blockIdx.x * blockDim.x + threadIdx.x;
    if (e < N_EDGES) {
        int p = atomicAdd(&g_cursor[src[e]], 1);
        g_csr[p] = e;
    }
}

// ---------------- edge MLPs for both ECC layers ------------------------------
__global__ void k_edge_mlp(const float* __restrict__ e,
                           const float* __restrict__ w0a, const float* __restrict__ b0a,
                           const float* __restrict__ w1a, const float* __restrict__ b1a,
                           const float* __restrict__ w0b, const float* __restrict__ b0b,
                           const float* __restrict__ w1b, const float* __restrict__ b1b) {
    __shared__ float sw0[2][S_DIM * H_DIM];
    __shared__ float sb0[2][H_DIM];
    __shared__ float sw1[2][H_DIM * H_DIM];
    __shared__ float sb1[2][H_DIM];
    for (int i = threadIdx.x; i < S_DIM * H_DIM; i += blockDim.x) {
        sw0[0][i] = w0a[i]; sw0[1][i] = w0b[i];
    }
    for (int i = threadIdx.x; i < H_DIM; i += blockDim.x) {
        sb0[0][i] = b0a[i]; sb0[1][i] = b0b[i];
        sb1[0][i] = b1a[i]; sb1[1][i] = b1b[i];
    }
    for (int i = threadIdx.x; i < H_DIM * H_DIM; i += blockDim.x) {
        sw1[0][i] = w1a[i]; sw1[1][i] = w1b[i];
    }
    __syncthreads();

    int eid = blockIdx.x * blockDim.x + threadIdx.x;
    if (eid >= N_EDGES) return;
    float4 ev4 = *reinterpret_cast<const float4*>(e + eid * 4);
    float ev[4] = {ev4.x, ev4.y, ev4.z, ev4.w};

    #pragma unroll
    for (int set = 0; set < 2; set++) {
        float h0[H_DIM];
        #pragma unroll
        for (int j = 0; j < H_DIM; j++) {
            float a = sb0[set][j];
            #pragma unroll
            for (int s = 0; s < S_DIM; s++) a += ev[s] * sw0[set][s * H_DIM + j];
            h0[j] = fmaxf(a, 0.f);
        }
        float* dst = (set == 0 ? g_H1 : g_H2) + eid * H_DIM;
        #pragma unroll 5
        for (int j = 0; j < H_DIM; j++) {
            float a = sb1[set][j];
            #pragma unroll
            for (int k = 0; k < H_DIM; k++) a += h0[k] * sw1[set][k * H_DIM + j];
            dst[j] = fmaxf(a, 0.f);
        }
    }
}

// ---------------- ECC1 node precompute, tiled: 32 nodes per block ------------
// y1[n, h*32+c] = sum_f x[n,f]*wk1[h*192+f*32+c]; z1[n,c] = sum_f x[n,f]*bk1[f*32+c]
__global__ void k_y1(const float* __restrict__ x,
                     const float* __restrict__ wk1, const float* __restrict__ bk1) {
    __shared__ float sxT[F_IN][32];
    int nb = blockIdx.x * 32;
    int tid = threadIdx.x;
    if (tid < 32 * F_IN) {
        int n = tid / F_IN, f = tid % F_IN;
        sxT[f][n] = x[(nb + n) * F_IN + f];
    }
    __syncthreads();
    for (int j = tid; j < H_DIM * C1 + C1; j += 256) {
        float w[F_IN];
        if (j < H_DIM * C1) {
            int h = j >> 5, c = j & 31;
            #pragma unroll
            for (int f = 0; f < F_IN; f++) w[f] = wk1[h * (F_IN * C1) + f * C1 + c];
        } else {
            int c = j - H_DIM * C1;
            #pragma unroll
            for (int f = 0; f < F_IN; f++) w[f] = bk1[f * C1 + c];
        }
        #pragma unroll 4
        for (int n = 0; n < 32; n++) {
            float a = 0.f;
            #pragma unroll
            for (int f = 0; f < F_IN; f++) a += sxT[f][n] * w[f];
            if (j < H_DIM * C1) g_Y1[(nb + n) * (H_DIM * C1) + j] = a;
            else                g_Z1[(nb + n) * C1 + (j - H_DIM * C1)] = a;
        }
    }
}

// ---------------- ECC1 edge, CSR-grouped: 8 src nodes per block --------------
#define NB1 8
__global__ void k_ecc1_edge(const int* __restrict__ src, const int* __restrict__ tgt) {
    __shared__ float sy[NB1 * H_DIM * C1];   // 8 * 960 floats = 30 KB
    int nb = blockIdx.x * NB1;
    int tid = threadIdx.x;
    const float4* gy = (const float4*)(g_Y1 + (long long)nb * (H_DIM * C1));
    for (int i = tid; i < NB1 * H_DIM * C1 / 4; i += 256)
        ((float4*)sy)[i] = gy[i];
    __syncthreads();
    int rs = g_rowptr[nb], re = g_rowptr[nb + NB1];
    int gid = tid >> 5, lane = tid & 31;
    for (int pos = rs + gid; pos < re; pos += 8) {
        int eid = g_csr[pos];
        int s = src[eid], t = tgt[eid];
        int ln = s - nb;
        const float* hh = g_H1 + eid * H_DIM;
        const float* y = sy + ln * (H_DIM * C1) + lane;
        float acc = g_Z1[s * C1 + lane];
        #pragma unroll
        for (int h = 0; h < H_DIM; h++) acc += hh[h] * y[h * C1];
        atomicAdd(&g_AGG1[t * C1 + lane], acc);
    }
}

// ---------------- ECC1 node update -------------------------------------------
__global__ void k_x1(const float* __restrict__ x,
                     const float* __restrict__ root1, const float* __restrict__ bias1) {
    int idx = blockIdx.x * blockDim.x + threadIdx.x;
    if (idx >= N_NODES * C1) return;
    int n = idx >> 5, c = idx & 31;
    float a = g_AGG1[idx] + bias1[c];
    #pragma unroll
    for (int f = 0; f < F_IN; f++) a += x[n * F_IN + f] * root1[f * C1 + c];
    g_X1[idx] = fmaxf(a, 0.f);
}

// ---------------- ECC2 node precompute, tiled 32 nodes x 256 cols, f32x2 -----
// cols 0..1919 -> y2[n, h*64+c]; cols 1920..1983 -> z2[n,c]
__global__ void k_y2(const float* __restrict__ wk2, const float* __restrict__ bk2) {
    __shared__ float sxT[C1 * 36];   // [c1][node], row stride 36 (16B aligned)
    int nb = blockIdx.y * 32;
    int tid = threadIdx.x;
    for (int i = tid; i < 32 * C1; i += 256) {
        int n = i >> 5, c1 = i & 31;
        sxT[c1 * 36 + n] = g_X1[(nb + n) * C1 + c1];
    }
    __syncthreads();
    int j = blockIdx.x * 256 + tid;
    if (j >= H_DIM * C2 + C2) return;

    float w[C1];
    if (j < H_DIM * C2) {
        int h = j >> 6, c = j & 63;
        #pragma unroll 8
        for (int c1 = 0; c1 < C1; c1++) w[c1] = wk2[h * (C1 * C2) + c1 * C2 + c];
    } else {
        int c = j - H_DIM * C2;
        #pragma unroll 8
        for (int c1 = 0; c1 < C1; c1++) w[c1] = bk2[c1 * C2 + c];
    }

    unsigned long long acc2[16];
    #pragma unroll
    for (int q = 0; q < 16; q++) acc2[q] = 0ull;  // +0.0f pair

    #pragma unroll 8
    for (int c1 = 0; c1 < C1; c1++) {
        unsigned long long wp = pk2(w[c1], w[c1]);
        const unsigned long long* xp = (const unsigned long long*)&sxT[c1 * 36];
        #pragma unroll
        for (int q = 0; q < 16; q++) acc2[q] = fma2(xp[q], wp, acc2[q]);
    }

    #pragma unroll
    for (int q = 0; q < 16; q++) {
        float a0, a1;
        upk2(acc2[q], a0, a1);
        int n0 = nb + 2 * q, n1 = n0 + 1;
        if (j < H_DIM * C2) {
            g_Y2[n0 * (H_DIM * C2) + j] = a0;
            g_Y2[n1 * (H_DIM * C2) + j] = a1;
        } else {
            int c = j - H_DIM * C2;
            g_Z2[n0 * C2 + c] = a0;
            g_Z2[n1 * C2 + c] = a1;
        }
    }
}

// ---------------- ECC2 edge, CSR-grouped: 4 src nodes per block, f32x2 -------
#define NB2 4
__global__ void k_ecc2_edge(const int* __restrict__ src, const int* __restrict__ tgt) {
    __shared__ float sy[NB2 * H_DIM * C2];   // 4 * 1920 floats = 30 KB
    int nb = blockIdx.x * NB2;
    int tid = threadIdx.x;
    const float4* gy = (const float4*)(g_Y2 + (long long)nb * (H_DIM * C2));
    for (int i = tid; i < NB2 * H_DIM * C2 / 4; i += 256)
        ((float4*)sy)[i] = gy[i];
    __syncthreads();
    int rs = g_rowptr[nb], re = g_rowptr[nb + NB2];
    int gid = tid >> 5, lane = tid & 31;   // lane -> c2 pair (2*lane, 2*lane+1)
    for (int pos = rs + gid; pos < re; pos += 8) {
        int eid = g_csr[pos];
        int s = src[eid], t = tgt[eid];
        int ln = s - nb;
        const float* hh = g_H2 + eid * H_DIM;
        const unsigned long long* yrow =
            (const unsigned long long*)(sy + ln * (H_DIM * C2)) + lane;
        float2 z = *(const float2*)(g_Z2 + s * C2 + lane * 2);
        unsigned long long acc = pk2(z.x, z.y);
        #pragma unroll
        for (int h = 0; h < H_DIM; h++) {
            float hv = hh[h];
            acc = fma2(yrow[h * 32], pk2(hv, hv), acc);
        }
        float a0, a1;
        upk2(acc, a0, a1);
        atomicAdd(&g_AGG2[t * C2 + lane * 2], a0);
        atomicAdd(&g_AGG2[t * C2 + lane * 2 + 1], a1);
    }
}

// ---------------- ECC2 node update -------------------------------------------
__global__ void k_x2(const float* __restrict__ root2, const float* __restrict__ bias2) {
    int idx = blockIdx.x * blockDim.x + threadIdx.x;
    if (idx >= N_NODES * C2) return;
    int n = idx >> 6, c = idx & 63;
    float a = g_AGG2[idx] + bias2[c];
    #pragma unroll 8
    for (int c1 = 0; c1 < C1; c1++) a += g_X1[n * C1 + c1] * root2[c1 * C2 + c];
    g_X2[idx] = fmaxf(a, 0.f);
}

// ---------------- GCN: xw = x2 @ gcn_W ---------------------------------------
__global__ void k_xw(const float* __restrict__ gcnW) {
    int idx = blockIdx.x * blockDim.x + threadIdx.x;
    if (idx >= N_NODES * C3) return;
    int n = idx >> 5, c = idx & 31;
    float a = 0.f;
    #pragma unroll 8
    for (int c2 = 0; c2 < C2; c2++) a += g_X2[n * C2 + c2] * gcnW[c2 * C3 + c];
    g_XW[idx] = a;
}

// ---------------- GCN weighted scatter (includes self loops) -----------------
__global__ void k_gcn_edge(const int* __restrict__ gsrc, const int* __restrict__ gtgt,
                           const float* __restrict__ gw) {
    int wid = (blockIdx.x * blockDim.x + threadIdx.x) >> 5;
    int lane = threadIdx.x & 31;
    if (wid >= EN_EDGES) return;
    int s = gsrc[wid], t = gtgt[wid];
    float w = gw[wid];
    atomicAdd(&g_ACC3[t * C3 + lane], w * g_XW[s * C3 + lane]);
}

// ---------------- relu + bias + global sum pool ------------------------------
__global__ void k_pool(const int* __restrict__ seg, const float* __restrict__ gcn_b,
                       float* __restrict__ out) {
    int idx = blockIdx.x * blockDim.x + threadIdx.x;
    if (idx >= N_NODES * C3) return;
    int n = idx >> 5, c = idx & 31;
    float v = fmaxf(g_ACC3[idx] + gcn_b[c], 0.f);
    atomicAdd(&out[seg[n] * C3 + c], v);
}

// =============================================================================
extern "C" void kernel_launch(void* const* d_in, const int* in_sizes, int n_in,
                              void* d_out, int out_size) {
    const float* x       = (const float*)d_in[0];
    const float* e       = (const float*)d_in[1];
    const int*   src     = (const int*)d_in[2];
    const int*   tgt     = (const int*)d_in[3];
    const int*   seg     = (const int*)d_in[4];
    const int*   gsrc    = (const int*)d_in[5];
    const int*   gtgt    = (const int*)d_in[6];
    const float* gw      = (const float*)d_in[7];
    const float* e1_w0   = (const float*)d_in[8];
    const float* e1_b0   = (const float*)d_in[9];
    const float* e1_w1   = (const float*)d_in[10];
    const float* e1_b1   = (const float*)d_in[11];
    const float* e1_wk   = (const float*)d_in[12];
    const float* e1_bk   = (const float*)d_in[13];
    const float* e1_root = (const float*)d_in[14];
    const float* e1_bias = (const float*)d_in[15];
    const float* e2_w0   = (const float*)d_in[16];
    const float* e2_b0   = (const float*)d_in[17];
    const float* e2_w1   = (const float*)d_in[18];
    const float* e2_b1   = (const float*)d_in[19];
    const float* e2_wk   = (const float*)d_in[20];
    const float* e2_bk   = (const float*)d_in[21];
    const float* e2_root = (const float*)d_in[22];
    const float* e2_bias = (const float*)d_in[23];
    const float* gcn_W   = (const float*)d_in[24];
    const float* gcn_b   = (const float*)d_in[25];
    float* out = (float*)d_out;

    // zero accumulators + degree + output
    k_zero<<<(N_NODES * C2 + 255) / 256, 256>>>(out, out_size);

    // CSR by src (recomputed each call; deterministic work)
    k_hist<<<(N_EDGES + 255) / 256, 256>>>(src);
    k_scan<<<1, 1024>>>();
    k_scatter<<<(N_EDGES + 255) / 256, 256>>>(src);

    // edge MLPs for both ECC layers
    k_edge_mlp<<<N_EDGES / 256, 256>>>(e, e1_w0, e1_b0, e1_w1, e1_b1,
                                          e2_w0, e2_b0, e2_w1, e2_b1);

    // ECC1
    k_y1<<<N_NODES / 32, 256>>>(x, e1_wk, e1_bk);
    k_ecc1_edge<<<N_NODES / NB1, 256>>>(src, tgt);
    k_x1<<<(N_NODES * C1) / 256, 256>>>(x, e1_root, e1_bias);

    // ECC2
    k_y2<<<dim3(8, N_NODES / 32), 256>>>(e2_wk, e2_bk);
    k_ecc2_edge<<<N_NODES / NB2, 256>>>(src, tgt);
    k_x2<<<(N_NODES * C2) / 256, 256>>>(e2_root, e2_bias);

    // GCN + pool
    k_xw<<<(N_NODES * C3) / 256, 256>>>(gcn_W);
    k_gcn_edge<<<(EN_EDGES * 32 + 255) / 256, 256>>>(gsrc, gtgt, gw);
    k_pool<<<(N_NODES * C3) / 256, 256>>>(seg, gcn_b, out);
}